// round 12
// baseline (speedup 1.0000x reference)
#include <cuda_runtime.h>
#include <cuda_bf16.h>
#include <math_constants.h>
#include <cstdint>

// Problem constants
#define NROW 8192          // B * N  (N = 16^3 pooled voxels per batch)
#define NPB  4096          // rows per batch
#define KS_C 4             // key splits for attention kernel
#define NB   (NPB / (KS_C * 64))   // 16 key-blocks per split
#define NTILE 2048         // conv tiles (16 wp x 16 hp x 2 b x 4 dq)
#define CGRID 296          // persistent conv grid (2 CTAs/SM x 148)

// kattn smem (floats): double buffer of {Fb0[64][12], Fb1[64][12], Vt[64][68]}
#define SM2_FB0  0
#define SM2_FB1  768
#define SM2_VT   1536
#define SM2_BUF  5888
#define SM2_P    (2 * SM2_BUF)          // 11776
#define SM2_LS   (SM2_P + 4 * 32 * 68)  // 20480
#define SM2_TOTAL (SM2_LS + 256)        // 20736 floats = 82944 B

// conv smem (floats): Wb bf16 pairs [8 chunks][96 ch][80B] = 61440 B;
// Xb bf16 pairs [2 spl][8 chunks][32 rows][48B] = 24576 B (Y [32][100] aliased);
// bias 128.
#define P4_WB  0                        // 15360 floats
#define P4_XB  15360                    // 6144 floats
#define P4_BS  21504                    // 128
#define P4_TOTAL 21632                  // floats = 86528 B

// ---- mma.sync (sm_80+; works at base sm_100 target) ----
__device__ __forceinline__ void mma_tf32(float* c, const uint32_t* a, const uint32_t* b) {
    asm volatile("mma.sync.aligned.m16n8k8.row.col.f32.tf32.tf32.f32 "
        "{%0,%1,%2,%3}, {%4,%5,%6,%7}, {%8,%9}, {%0,%1,%2,%3};"
        : "+f"(c[0]), "+f"(c[1]), "+f"(c[2]), "+f"(c[3])
        : "r"(a[0]), "r"(a[1]), "r"(a[2]), "r"(a[3]), "r"(b[0]), "r"(b[1]));
}
__device__ __forceinline__ void mma_bf16(float* c, const uint32_t* a, const uint32_t* b) {
    asm volatile("mma.sync.aligned.m16n8k16.row.col.f32.bf16.bf16.f32 "
        "{%0,%1,%2,%3}, {%4,%5,%6,%7}, {%8,%9}, {%0,%1,%2,%3};"
        : "+f"(c[0]), "+f"(c[1]), "+f"(c[2]), "+f"(c[3])
        : "r"(a[0]), "r"(a[1]), "r"(a[2]), "r"(a[3]), "r"(b[0]), "r"(b[1]));
}
__device__ __forceinline__ uint32_t f2tf32(float v) {
    uint32_t r; asm("cvt.rna.tf32.f32 %0, %1;" : "=r"(r) : "f"(v)); return r;
}
__device__ __forceinline__ uint32_t packbf2(float lo, float hi) {
    __nv_bfloat162 t = __floats2bfloat162_rn(lo, hi);
    return *(uint32_t*)&t;
}
__device__ __forceinline__ void ldm_x4(uint32_t* r, uint32_t addr) {
    asm volatile("ldmatrix.sync.aligned.m8n8.x4.shared.b16 {%0,%1,%2,%3}, [%4];"
        : "=r"(r[0]), "=r"(r[1]), "=r"(r[2]), "=r"(r[3]) : "r"(addr));
}

__device__ __forceinline__ void cp16(uint32_t dst, const void* src) {
    asm volatile("cp.async.cg.shared.global [%0], [%1], 16;" :: "r"(dst), "l"(src));
}
#define CP_COMMIT() asm volatile("cp.async.commit_group;" ::: "memory")
#define CP_WAIT(n)  asm volatile("cp.async.wait_group %0;" :: "n"(n) : "memory")

__device__ __forceinline__ uint32_t smem_u32(const void* p) {
    uint32_t a;
    asm("{ .reg .u64 t; cvta.to.shared.u64 t, %1; cvt.u32.u64 %0, t; }" : "=r"(a) : "l"(p));
    return a;
}

// ---------------- scratch (static device memory; no allocations) -------------
__device__ __nv_bfloat16 g_Fb0[NROW * 16];   // keys, bf16 primary
__device__ __nv_bfloat16 g_Fb1[NROW * 16];   // keys, bf16 residual
__device__ float g_G[NROW * 16];             // queries (full fp32)
__device__ float g_Ht[2][64][NPB];           // values TRANSPOSED, tf32-rounded
__device__ float g_O[KS_C][NROW * 64];       // partial (unnormalized) attn outputs
__device__ float g_Ls[KS_C * NROW];          // per-split row exp-sum

// =============================================================================
// Kernel A: PERSISTENT conv, full 3x bf16 (value+residual splits of X and W).
// Grid 296 x 256 (2 CTAs/SM, smem 86.5KB). W split once into bf16 pairs
// ([chunk][ch][b0|b1], 80B stride -> one ldm_x4 = both B-frags). X: per tile,
// each thread LDGs 16 floats into regs (issued a tile early), converts to
// bf16 pairs, stores into 48B-stride Xb for ldm_x4 A-frags. Hot loop has NO
// scalar split ALU: per k16 chunk/warp: 2 X-ldm + 3 W-ldm + 9 mma.
// Y epilogue tile aliases Xb.
// =============================================================================
__global__ void __launch_bounds__(256, 2) kconvpool(
    const float* __restrict__ x,
    const float* __restrict__ Wf, const float* __restrict__ bf,
    const float* __restrict__ Wg, const float* __restrict__ bg,
    const float* __restrict__ Wh, const float* __restrict__ bh)
{
    extern __shared__ float sm[];
    float* bsm = sm + P4_BS;
    float* Ys  = sm + P4_XB;                 // aliased on Xb
    const uint32_t wbB = smem_u32(sm + P4_WB);
    const uint32_t xbB = smem_u32(sm + P4_XB);

    const int tid = threadIdx.x;
    const int w = tid >> 5, lane = tid & 31;
    const int lr = lane >> 2, lc = lane & 3;
    const int wm = w >> 2, wn = w & 3;
    const int m0 = wm * 16;

    // this thread's X slice: one (row, chunk)
    const int xrow = tid >> 3;               // 0..31 local voxel
    const int xchk = tid & 7;                // 0..7 k16 chunk
    const int xrun = xrow >> 3;              // hh*2+ww
    const int xd   = xrow & 7;               // local d
    const int xhh = xrun >> 1, xww = xrun & 1;

    // ---- stage W once: bf16 pairs ----
    for (int i = tid; i < 96 * 128; i += 256) {
        int c = i >> 7, k = i & 127;
        float v;
        if (c < 16)      v = Wf[k * 16 + c];
        else if (c < 32) v = Wg[k * 16 + (c - 16)];
        else             v = Wh[k * 64 + (c - 32)];
        __nv_bfloat16 b0 = __float2bfloat16(v);
        __nv_bfloat16 b1 = __float2bfloat16(v - __bfloat162float(b0));
        uint32_t a = wbB + (uint32_t)((k >> 4) * 7680 + c * 80 + (k & 15) * 2);
        asm volatile("st.shared.b16 [%0], %1;" :: "r"(a), "h"(*(uint16_t*)&b0));
        asm volatile("st.shared.b16 [%0], %1;" :: "r"(a + 32), "h"(*(uint16_t*)&b1));
    }
    if (tid < 96)
        bsm[tid] = (tid < 16) ? bf[tid] : (tid < 32 ? bg[tid - 16] : bh[tid - 32]);

    // ---- prefetch first tile's X into regs ----
    float4 xr[4];
    {
        const int tile = blockIdx.x;
        const int wp = tile & 15, hp = (tile >> 4) & 15;
        const int q = tile >> 8, b = q >> 2, dq = q & 3;
        const float4* src = (const float4*)(x +
            ((((long)b * 32 + 2 * hp + xhh) * 32 + 2 * wp + xww) * 32
             + dq * 8 + xd) * 128 + xchk * 16);
#pragma unroll
        for (int j = 0; j < 4; ++j) xr[j] = src[j];
    }

    for (int tile = blockIdx.x; tile < NTILE; tile += CGRID) {
        __syncthreads();   // prior tile's epilogue Y reads done (Xb reusable)

        // ---- convert this tile's X regs -> Xb bf16 pairs ----
        {
            float e[16];
#pragma unroll
            for (int j = 0; j < 4; ++j) {
                e[4 * j] = xr[j].x; e[4 * j + 1] = xr[j].y;
                e[4 * j + 2] = xr[j].z; e[4 * j + 3] = xr[j].w;
            }
            uint32_t b0w[8], b1w[8];
#pragma unroll
            for (int p = 0; p < 8; ++p) {
                float v0 = e[2 * p], v1 = e[2 * p + 1];
                __nv_bfloat16 h0 = __float2bfloat16(v0);
                __nv_bfloat16 h1 = __float2bfloat16(v1);
                __nv_bfloat162 pk; pk.x = h0; pk.y = h1;
                b0w[p] = *(uint32_t*)&pk;
                b1w[p] = packbf2(v0 - __bfloat162float(h0),
                                 v1 - __bfloat162float(h1));
            }
            uint32_t a0 = xbB + (uint32_t)((xchk * 32 + xrow) * 48);
            uint32_t a1 = xbB + (uint32_t)(((8 + xchk) * 32 + xrow) * 48);
            asm volatile("st.shared.v4.b32 [%0], {%1,%2,%3,%4};"
                :: "r"(a0), "r"(b0w[0]), "r"(b0w[1]), "r"(b0w[2]), "r"(b0w[3]));
            asm volatile("st.shared.v4.b32 [%0], {%1,%2,%3,%4};"
                :: "r"(a0 + 16), "r"(b0w[4]), "r"(b0w[5]), "r"(b0w[6]), "r"(b0w[7]));
            asm volatile("st.shared.v4.b32 [%0], {%1,%2,%3,%4};"
                :: "r"(a1), "r"(b1w[0]), "r"(b1w[1]), "r"(b1w[2]), "r"(b1w[3]));
            asm volatile("st.shared.v4.b32 [%0], {%1,%2,%3,%4};"
                :: "r"(a1 + 16), "r"(b1w[4]), "r"(b1w[5]), "r"(b1w[6]), "r"(b1w[7]));
        }

        // ---- issue next tile's X LDGs (latency hidden under MMA) ----
        const int nxt = tile + CGRID;
        if (nxt < NTILE) {
            const int wp = nxt & 15, hp = (nxt >> 4) & 15;
            const int q = nxt >> 8, b = q >> 2, dq = q & 3;
            const float4* src = (const float4*)(x +
                ((((long)b * 32 + 2 * hp + xhh) * 32 + 2 * wp + xww) * 32
                 + dq * 8 + xd) * 128 + xchk * 16);
#pragma unroll
            for (int j = 0; j < 4; ++j) xr[j] = src[j];
        }
        __syncthreads();   // Xb ready

        // ---- MMA mainloop: 8 chunks x 3 n-tiles x 3-term bf16 ----
        float acc[3][4];
#pragma unroll
        for (int t = 0; t < 3; ++t)
#pragma unroll
            for (int i = 0; i < 4; ++i) acc[t][i] = 0.f;

        const uint32_t xoffA = (uint32_t)((m0 + (lane & 7) + ((lane >> 3) & 1) * 8) * 48
                                          + (lane >> 4) * 16);
#pragma unroll
        for (int chunk = 0; chunk < 8; ++chunk) {
            uint32_t xa0[4], xa1[4];
            ldm_x4(xa0, xbB + (uint32_t)(chunk * 1536) + xoffA);
            ldm_x4(xa1, xbB + (uint32_t)((8 + chunk) * 1536) + xoffA);
#pragma unroll
            for (int tt = 0; tt < 3; ++tt) {
                const int t = wn + tt * 4;
                uint32_t wb[4];
                ldm_x4(wb, wbB + (uint32_t)(chunk * 7680 + (t * 8 + (lane & 7)) * 80
                                            + (lane >> 3) * 16));
                mma_bf16(acc[tt], xa0, wb);
                mma_bf16(acc[tt], xa0, wb + 2);
                mma_bf16(acc[tt], xa1, wb);
            }
        }
        __syncthreads();   // all Xb reads done -> alias as Y

        // ---- C-frags -> Y [voxel][c] (stride 100) ----
#pragma unroll
        for (int tt = 0; tt < 3; ++tt) {
            const int t = wn + tt * 4;
            *(float2*)&Ys[(m0 + lr) * 100 + t * 8 + 2 * lc] =
                make_float2(acc[tt][0], acc[tt][1]);
            *(float2*)&Ys[(m0 + lr + 8) * 100 + t * 8 + 2 * lc] =
                make_float2(acc[tt][2], acc[tt][3]);
        }
        __syncthreads();

        // ---- maxpool + bias + writeout: 4 dpl x 96 c ----
        const int wp = tile & 15, hp = (tile >> 4) & 15;
        const int q = tile >> 8, b = q >> 2, dq = q & 3;
        for (int i = tid; i < 384; i += 256) {
            int dpl = i & 3;
            int cc  = i >> 2;
            float m = -CUDART_INF_F;
#pragma unroll
            for (int r = 0; r < 4; ++r)
#pragma unroll
                for (int dd = 0; dd < 2; ++dd)
                    m = fmaxf(m, Ys[(r * 8 + 2 * dpl + dd) * 100 + cc]);
            m += bsm[cc];
            int row = ((b * 16 + hp) * 16 + wp) * 16 + dq * 4 + dpl;
            if (cc < 16) {
                __nv_bfloat16 b0 = __float2bfloat16(m);
                g_Fb0[row * 16 + cc] = b0;
                g_Fb1[row * 16 + cc] = __float2bfloat16(m - __bfloat162float(b0));
            } else if (cc < 32) {
                g_G[row * 16 + (cc - 16)] = m;
            } else {
                g_Ht[b][cc - 32][row & (NPB - 1)] = __uint_as_float(f2tf32(m));
            }
        }
    }
}

// =============================================================================
// Kernel C: flash attention; MMA1 = 3x bf16, MMA2 = tf32 (P fed as raw fp32 —
// HW truncates to tf32; l sums the same raw values so normalization cancels).
// =============================================================================
__global__ void __launch_bounds__(256, 2) kattn()
{
    extern __shared__ float sm[];
    const uint32_t smb = smem_u32(sm);

    const int tid = threadIdx.x;
    const int w = tid >> 5, lane = tid & 31;
    const int lr = lane >> 2, lc = lane & 3;
    const int wm = w >> 1, wn = w & 1;

    const int qb = blockIdx.x, ks = blockIdx.y;
    const int rows0 = qb * 128 + wm * 32;
    const int b = qb >> 5;
    const int kloc0 = ks * (NPB / KS_C);
    const long kg0 = (long)b * NPB + kloc0;

    float* Pw = sm + SM2_P + wm * (32 * 68);
    const uint32_t PwB = smb + (uint32_t)((SM2_P + wm * 32 * 68) * 4);
    float* s_l0 = sm + SM2_LS;
    float* s_l1 = sm + SM2_LS + 128;

    uint32_t qb0[2][4], qb1[2][4];
#pragma unroll
    for (int ml = 0; ml < 2; ++ml) {
        int r0 = rows0 + ml * 16;
#pragma unroll
        for (int j = 0; j < 4; ++j) {
            int row = r0 + lr + (j & 1) * 8;
            int c0  = 2 * lc + (j >> 1) * 8;
            float2 v = *(const float2*)&g_G[(long)row * 16 + c0];
            __nv_bfloat16 h0 = __float2bfloat16(v.x);
            __nv_bfloat16 h1 = __float2bfloat16(v.y);
            qb0[ml][j] = packbf2(v.x, v.y);
            qb1[ml][j] = packbf2(v.x - __bfloat162float(h0),
                                 v.y - __bfloat162float(h1));
        }
    }

    float o[2][4][4];
#pragma unroll
    for (int ml = 0; ml < 2; ++ml)
#pragma unroll
        for (int t = 0; t < 4; ++t)
#pragma unroll
            for (int i = 0; i < 4; ++i) o[ml][t][i] = 0.f;
    float ls[2][2] = {{0.f, 0.f}, {0.f, 0.f}};

    {
        uint32_t base = smb;
        int key = tid >> 2, sc = tid & 3;
        int spl = sc >> 1, ch = sc & 1;
        const __nv_bfloat16* gF = spl ? g_Fb1 : g_Fb0;
        cp16(base + (uint32_t)(spl * 3072 + key * 48 + ch * 16),
             (const char*)(gF + (kg0 + key) * 16) + ch * 16);
#pragma unroll
        for (int r = 0; r < 4; ++r) {
            int i = r * 256 + tid;
            int c = i >> 4, kc = i & 15;
            cp16(base + (uint32_t)((SM2_VT + c * 68 + kc * 4) * 4),
                 (const char*)&g_Ht[b][c][kloc0 + kc * 4]);
        }
        CP_COMMIT();
    }

    for (int kb = 0; kb < NB; ++kb) {
        __syncthreads();
        if (kb + 1 < NB) {
            const int kl = kloc0 + (kb + 1) * 64;
            const long kg = (long)b * NPB + kl;
            uint32_t base = smb + (uint32_t)(((kb + 1) & 1) * SM2_BUF * 4);
            int key = tid >> 2, sc = tid & 3;
            int spl = sc >> 1, ch = sc & 1;
            const __nv_bfloat16* gF = spl ? g_Fb1 : g_Fb0;
            cp16(base + (uint32_t)(spl * 3072 + key * 48 + ch * 16),
                 (const char*)(gF + (kg + key) * 16) + ch * 16);
#pragma unroll
            for (int r = 0; r < 4; ++r) {
                int i = r * 256 + tid;
                int c = i >> 4, kc = i & 15;
                cp16(base + (uint32_t)((SM2_VT + c * 68 + kc * 4) * 4),
                     (const char*)&g_Ht[b][c][kl + kc * 4]);
            }
            CP_COMMIT();
            CP_WAIT(1);
        } else {
            CP_WAIT(0);
        }
        __syncthreads();

        const uint32_t bufB = smb + (uint32_t)((kb & 1) * SM2_BUF * 4);

        // ---- MMA1 (bf16) + exp + P store ----
#pragma unroll
        for (int p = 0; p < 2; ++p) {
            uint32_t rowk = (uint32_t)(((wn * 4 + 2 * p) * 8 + (lane & 7)
                                        + (lane >> 4) * 8) * 48
                                       + ((lane >> 3) & 1) * 16);
            uint32_t fb0[4], fb1[4];
            ldm_x4(fb0, bufB + rowk);
            ldm_x4(fb1, bufB + 3072u + rowk);
#pragma unroll
            for (int i2 = 0; i2 < 2; ++i2) {
                const int ktg = wn * 4 + 2 * p + i2;
#pragma unroll
                for (int ml = 0; ml < 2; ++ml) {
                    float acc[4] = {0.f, 0.f, 0.f, 0.f};
                    mma_bf16(acc, qb0[ml], fb0 + 2 * i2);
                    mma_bf16(acc, qb0[ml], fb1 + 2 * i2);
                    mma_bf16(acc, qb1[ml], fb0 + 2 * i2);
                    float p0 = __expf(acc[0]);
                    float p1 = __expf(acc[1]);
                    float p2 = __expf(acc[2]);
                    float p3 = __expf(acc[3]);
                    ls[ml][0] += p0 + p1;
                    ls[ml][1] += p2 + p3;
                    *(float2*)&Pw[(ml * 16 + lr) * 68 + ktg * 8 + 2 * lc] =
                        make_float2(p0, p1);
                    *(float2*)&Pw[(ml * 16 + lr + 8) * 68 + ktg * 8 + 2 * lc] =
                        make_float2(p2, p3);
                }
            }
        }

        asm volatile("bar.sync %0, 64;" :: "r"(1 + wm) : "memory");

        // ---- MMA2 (tf32): O += P.V ----
#pragma unroll
        for (int kk = 0; kk < 8; ++kk) {
            uint32_t pa[2][4];
#pragma unroll
            for (int ml = 0; ml < 2; ++ml) {
                uint32_t addr = PwB + (uint32_t)(((ml * 16 + (lane & 7) + ((lane >> 3) & 1) * 8) * 68
                                 + kk * 8 + (lane >> 4) * 4) * 4);
                ldm_x4(pa[ml], addr);
            }
#pragma unroll
            for (int ctp = 0; ctp < 2; ++ctp) {
                uint32_t vb[4];
                uint32_t addr = bufB + (uint32_t)((SM2_VT
                                 + ((wn * 4 + ctp * 2) * 8 + (lane >> 4) * 8 + (lane & 7)) * 68
                                 + kk * 8 + ((lane >> 3) & 1) * 4) * 4);
                ldm_x4(vb, addr);
#pragma unroll
                for (int ml = 0; ml < 2; ++ml) {
                    mma_tf32(o[ml][ctp * 2 + 0], pa[ml], vb);
                    mma_tf32(o[ml][ctp * 2 + 1], pa[ml], vb + 2);
                }
            }
        }
    }

    // ---- epilogue ----
#pragma unroll
    for (int ml = 0; ml < 2; ++ml)
#pragma unroll
        for (int hh = 0; hh < 2; ++hh) {
            float v = ls[ml][hh];
            v += __shfl_xor_sync(0xffffffffu, v, 1);
            v += __shfl_xor_sync(0xffffffffu, v, 2);
            ls[ml][hh] = v;
        }
    if (lc == 0) {
        float* dst = wn ? s_l1 : s_l0;
#pragma unroll
        for (int ml = 0; ml < 2; ++ml) {
            dst[wm * 32 + ml * 16 + lr]     = ls[ml][0];
            dst[wm * 32 + ml * 16 + lr + 8] = ls[ml][1];
        }
    }
    __syncthreads();
    if (tid < 128)
        g_Ls[ks * NROW + qb * 128 + tid] = s_l0[tid] + s_l1[tid];

#pragma unroll
    for (int ml = 0; ml < 2; ++ml)
#pragma unroll
        for (int ct = 0; ct < 4; ++ct) {
            int r0 = rows0 + ml * 16;
            int c0 = wn * 32 + ct * 8 + 2 * lc;
            *(float2*)&g_O[ks][(long)(r0 + lr) * 64 + c0] =
                make_float2(o[ml][ct][0], o[ml][ct][1]);
            *(float2*)&g_O[ks][(long)(r0 + lr + 8) * 64 + c0] =
                make_float2(o[ml][ct][2], o[ml][ct][3]);
        }
}

// =============================================================================
// Kernel E (fused): merge key-splits, U = o @ Wv + bv at pooled res, then
// out = gamma * upsample(U) + x written directly.
// =============================================================================
__global__ void __launch_bounds__(128) kout(const float* __restrict__ Wv,
                                           const float* __restrict__ bv,
                                           const float* __restrict__ x,
                                           const float* __restrict__ gamma,
                                           float* __restrict__ out)
{
    __shared__ float os[16 * 64];
    __shared__ float linv[16];
    const int row0 = blockIdx.x * 16;
    const int tid = threadIdx.x;

    if (tid < 16) {
        int r = row0 + tid;
        float l = 0.f;
#pragma unroll
        for (int s = 0; s < KS_C; ++s) l += g_Ls[s * NROW + r];
        linv[tid] = 1.f / l;
    }
    __syncthreads();

    for (int i = tid; i < 1024; i += 128) {
        int rlc = i >> 6;
        float ssum = 0.f;
#pragma unroll
        for (int s = 0; s < KS_C; ++s) ssum += g_O[s][(long)row0 * 64 + i];
        os[i] = ssum * linv[rlc];
    }
    __syncthreads();

    float acc[16];
    const float bb = bv[tid];
#pragma unroll
    for (int n = 0; n < 16; ++n) acc[n] = bb;

    for (int k = 0; k < 64; ++k) {
        float wv = Wv[k * 128 + tid];
#pragma unroll
        for (int n = 0; n < 16; ++n) acc[n] += os[n * 64 + k] * wv;
    }

    const float g = __ldg(gamma);
#pragma unroll
    for (int n = 0; n < 16; ++n) {
        int row = row0 + n;
        int b = row >> 12, hp = (row >> 8) & 15, wp = (row >> 4) & 15, dp = row & 15;
        float u = g * acc[n];
#pragma unroll
        for (int v = 0; v < 8; ++v) {
            int hh = v >> 2, ww = (v >> 1) & 1, dd = v & 1;
            long gi = ((((long)b * 32 + 2 * hp + hh) * 32 + 2 * wp + ww) * 32
                       + 2 * dp + dd) * 128 + tid;
            out[gi] = u + x[gi];
        }
    }
}

// =============================================================================
extern "C" void kernel_launch(void* const* d_in, const int* in_sizes, int n_in,
                              void* d_out, int out_size)
{
    const float* x     = (const float*)d_in[0];
    const float* Wf    = (const float*)d_in[1];
    const float* bf    = (const float*)d_in[2];
    const float* Wg    = (const float*)d_in[3];
    const float* bg    = (const float*)d_in[4];
    const float* Wh    = (const float*)d_in[5];
    const float* bh    = (const float*)d_in[6];
    const float* Wv    = (const float*)d_in[7];
    const float* bv    = (const float*)d_in[8];
    const float* gamma = (const float*)d_in[9];
    float* out = (float*)d_out;

    (void)in_sizes; (void)n_in; (void)out_size;

    cudaFuncSetAttribute(kconvpool, cudaFuncAttributeMaxDynamicSharedMemorySize, P4_TOTAL * 4);
    cudaFuncSetAttribute(kattn,     cudaFuncAttributeMaxDynamicSharedMemorySize, SM2_TOTAL * 4);

    kconvpool<<<CGRID, 256, P4_TOTAL * 4>>>(x, Wf, bf, Wg, bg, Wh, bh);
    kattn<<<dim3(64, KS_C), 256, SM2_TOTAL * 4>>>();
    kout<<<512, 128>>>(Wv, bv, x, gamma, out);
}

// round 13
// speedup vs baseline: 1.0178x; 1.0178x over previous
#include <cuda_runtime.h>
#include <cuda_bf16.h>
#include <math_constants.h>
#include <cstdint>

// Problem constants
#define NROW 8192          // B * N  (N = 16^3 pooled voxels per batch)
#define NPB  4096          // rows per batch
#define KS_C 4             // key splits for attention kernel
#define NB   (NPB / (KS_C * 64))   // 16 key-blocks per split
#define NTILE 2048         // conv tiles (16 wp x 16 hp x 2 b x 4 dq)
#define CGRID 296          // persistent conv grid (2 CTAs/SM x 148)

// kattn smem (floats): double buffer of {Fb0[64][12], Fb1[64][12], Vt[64][68]}
#define SM2_FB0  0
#define SM2_FB1  768
#define SM2_VT   1536
#define SM2_BUF  5888
#define SM2_P    (2 * SM2_BUF)          // 11776
#define SM2_LS   (SM2_P + 4 * 32 * 68)  // 20480
#define SM2_TOTAL (SM2_LS + 256)        // 20736 floats = 82944 B

// persistent conv smem layout (floats) — R11 structure
#define P3_WHI 0                        // 96*132 = 12672
#define P3_WLO 12672                    // 32*132 = 4224
#define P3_X   16896                    // 2 x 32*132 = 8448
#define P3_Y   25344                    // 32*100 = 3200
#define P3_B   28544                    // 128
#define P3_TOTAL 28672                  // floats = 114688 B

// ---- mma.sync (sm_80+; works at base sm_100 target) ----
__device__ __forceinline__ void mma_tf32(float* c, const uint32_t* a, const uint32_t* b) {
    asm volatile("mma.sync.aligned.m16n8k8.row.col.f32.tf32.tf32.f32 "
        "{%0,%1,%2,%3}, {%4,%5,%6,%7}, {%8,%9}, {%0,%1,%2,%3};"
        : "+f"(c[0]), "+f"(c[1]), "+f"(c[2]), "+f"(c[3])
        : "r"(a[0]), "r"(a[1]), "r"(a[2]), "r"(a[3]), "r"(b[0]), "r"(b[1]));
}
__device__ __forceinline__ void mma_bf16(float* c, const uint32_t* a, const uint32_t* b) {
    asm volatile("mma.sync.aligned.m16n8k16.row.col.f32.bf16.bf16.f32 "
        "{%0,%1,%2,%3}, {%4,%5,%6,%7}, {%8,%9}, {%0,%1,%2,%3};"
        : "+f"(c[0]), "+f"(c[1]), "+f"(c[2]), "+f"(c[3])
        : "r"(a[0]), "r"(a[1]), "r"(a[2]), "r"(a[3]), "r"(b[0]), "r"(b[1]));
}
__device__ __forceinline__ uint32_t f2tf32(float v) {
    uint32_t r; asm("cvt.rna.tf32.f32 %0, %1;" : "=r"(r) : "f"(v)); return r;
}
__device__ __forceinline__ uint32_t packbf2(float lo, float hi) {
    __nv_bfloat162 t = __floats2bfloat162_rn(lo, hi);
    return *(uint32_t*)&t;
}
__device__ __forceinline__ void ldm_x4(uint32_t* r, uint32_t addr) {
    asm volatile("ldmatrix.sync.aligned.m8n8.x4.shared.b16 {%0,%1,%2,%3}, [%4];"
        : "=r"(r[0]), "=r"(r[1]), "=r"(r[2]), "=r"(r[3]) : "r"(addr));
}
__device__ __forceinline__ void ldm_x2(uint32_t* r, uint32_t addr) {
    asm volatile("ldmatrix.sync.aligned.m8n8.x2.shared.b16 {%0,%1}, [%2];"
        : "=r"(r[0]), "=r"(r[1]) : "r"(addr));
}

__device__ __forceinline__ void cp16(uint32_t dst, const void* src) {
    asm volatile("cp.async.cg.shared.global [%0], [%1], 16;" :: "r"(dst), "l"(src));
}
#define CP_COMMIT() asm volatile("cp.async.commit_group;" ::: "memory")
#define CP_WAIT(n)  asm volatile("cp.async.wait_group %0;" :: "n"(n) : "memory")

__device__ __forceinline__ uint32_t smem_u32(const void* p) {
    uint32_t a;
    asm("{ .reg .u64 t; cvta.to.shared.u64 t, %1; cvt.u32.u64 %0, t; }" : "=r"(a) : "l"(p));
    return a;
}

// ---------------- scratch (static device memory; no allocations) -------------
__device__ __nv_bfloat16 g_Fb0[NROW * 16];   // keys, bf16 primary
__device__ __nv_bfloat16 g_Fb1[NROW * 16];   // keys, bf16 residual
__device__ float g_G[NROW * 16];             // queries (full fp32)
__device__ float g_Ht[2][64][NPB];           // values TRANSPOSED, tf32-rounded
__device__ float g_O[KS_C][NROW * 64];       // partial (unnormalized) attn outputs
__device__ float g_Ls[KS_C * NROW];          // per-split row exp-sum

// =============================================================================
// Kernel A: PERSISTENT tensor-core conv (96 out ch) + 2x2x2 maxpool.
// R11 data path (cp.async X staging, tf32 hi/lo in-loop split, ldmatrix frag
// loads) but 384 threads = 12 warps (2m x 6n) for latency hiding (24 warps/SM
// at 2 CTAs/SM). Warp (wm, wn) owns m-tile wm and n-tiles {wn, wn+6}; the
// first is 3xtf32 when wn<4 (f,g channels), else 1x.
// =============================================================================
__device__ __forceinline__ void stage_x_tile(const float* __restrict__ x,
                                             uint32_t xsb, int buf, int tile, int tid)
{
    const int wp = tile & 15, hp = (tile >> 4) & 15;
    const int q = tile >> 8, b = q >> 2, dq = q & 3;
    for (int ci = tid; ci < 1024; ci += 384) {
        int run = ci >> 8;               // hh*2+ww
        int d   = (ci >> 5) & 7;
        int c16 = ci & 31;
        int hh = run >> 1, ww = run & 1;
        long gl = ((((long)b * 32 + 2 * hp + hh) * 32 + 2 * wp + ww) * 32
                   + dq * 8 + d) * 128 + c16 * 4;
        cp16(xsb + (uint32_t)((buf * 4224 + (run * 8 + d) * 132 + c16 * 4) * 4),
             (const char*)(x + gl));
    }
}

__global__ void __launch_bounds__(384, 2) kconvpool(
    const float* __restrict__ x,
    const float* __restrict__ Wf, const float* __restrict__ bf,
    const float* __restrict__ Wg, const float* __restrict__ bg,
    const float* __restrict__ Wh, const float* __restrict__ bh)
{
    extern __shared__ float sm[];
    float* Whi = sm + P3_WHI;     // [96][132]
    float* Wlo = sm + P3_WLO;     // [32][132]
    float* Xb  = sm + P3_X;       // [2][32][132]
    float* Ys  = sm + P3_Y;       // [32][100]
    float* bsm = sm + P3_B;       // [96]
    const uint32_t xsb  = smem_u32(Xb);
    const uint32_t whib = smem_u32(Whi);
    const uint32_t wlob = smem_u32(Wlo);

    const int tid = threadIdx.x;
    const int w = tid >> 5, lane = tid & 31;
    const int lr = lane >> 2, lc = lane & 3;
    const int wm = w / 6, wn = w - wm * 6;
    const int m0 = wm * 16;

    // prefetch first tile while staging W
    stage_x_tile(x, xsb, 0, blockIdx.x, tid);
    CP_COMMIT();

    for (int i = tid; i < 96 * 128; i += 384) {
        int c = i >> 7, k = i & 127;
        float v;
        if (c < 16)      v = Wf[k * 16 + c];
        else if (c < 32) v = Wg[k * 16 + (c - 16)];
        else             v = Wh[k * 64 + (c - 32)];
        float hi = __int_as_float(__float_as_int(v) & 0xffffe000u);
        Whi[c * 132 + k] = hi;
        if (c < 32) Wlo[c * 132 + k] = __uint_as_float(f2tf32(v - hi));
    }
    if (tid < 96)
        bsm[tid] = (tid < 16) ? bf[tid] : (tid < 32 ? bg[tid - 16] : bh[tid - 32]);

    int jbuf = 0;
    for (int tile = blockIdx.x; tile < NTILE; tile += CGRID, jbuf ^= 1) {
        const int nxt = tile + CGRID;
        if (nxt < NTILE) {
            stage_x_tile(x, xsb, jbuf ^ 1, nxt, tid);
            CP_COMMIT();
            CP_WAIT(1);
        } else {
            CP_WAIT(0);
        }
        __syncthreads();   // X(tile) ready; prior epilogue's Y reads done

        const int wp = tile & 15, hp = (tile >> 4) & 15;
        const int q = tile >> 8, b = q >> 2, dq = q & 3;
        const uint32_t xcb = xsb + (uint32_t)(jbuf * 4224 * 4);

        float acc[2][4];
#pragma unroll
        for (int t = 0; t < 2; ++t)
#pragma unroll
            for (int i = 0; i < 4; ++i) acc[t][i] = 0.f;

#pragma unroll
        for (int k0 = 0; k0 < 128; k0 += 8) {
            uint32_t xa[4];
            ldm_x4(xa, xcb + (uint32_t)(((m0 + (lane & 15)) * 132
                                         + k0 + (lane >> 4) * 4) * 4));
            uint32_t ah[4], al[4];
#pragma unroll
            for (int j = 0; j < 4; ++j) {
                float v = __uint_as_float(xa[j]);
                float h = __int_as_float(__float_as_int(v) & 0xffffe000u);
                ah[j] = __float_as_uint(h);
                al[j] = f2tf32(v - h);
            }
            // tile 0: t = wn (3xtf32 when wn<4 -> f,g channels)
            {
                uint32_t bh2[2];
                ldm_x2(bh2, whib + (uint32_t)(((wn * 8 + (lane & 7)) * 132
                                               + k0 + ((lane >> 3) & 1) * 4) * 4));
                mma_tf32(acc[0], ah, bh2);
                if (wn < 4) {
                    uint32_t bl2[2];
                    ldm_x2(bl2, wlob + (uint32_t)(((wn * 8 + (lane & 7)) * 132
                                                   + k0 + ((lane >> 3) & 1) * 4) * 4));
                    mma_tf32(acc[0], al, bh2);
                    mma_tf32(acc[0], ah, bl2);
                }
            }
            // tile 1: t = wn + 6 (h channels, 1xtf32)
            {
                uint32_t bh2[2];
                ldm_x2(bh2, whib + (uint32_t)((((wn + 6) * 8 + (lane & 7)) * 132
                                               + k0 + ((lane >> 3) & 1) * 4) * 4));
                mma_tf32(acc[1], ah, bh2);
            }
        }

        // ---- C-frags -> Y [voxel][c] (stride 100) ----
#pragma unroll
        for (int tt = 0; tt < 2; ++tt) {
            const int t = wn + tt * 6;
            *(float2*)&Ys[(m0 + lr) * 100 + t * 8 + 2 * lc] =
                make_float2(acc[tt][0], acc[tt][1]);
            *(float2*)&Ys[(m0 + lr + 8) * 100 + t * 8 + 2 * lc] =
                make_float2(acc[tt][2], acc[tt][3]);
        }
        __syncthreads();

        // ---- maxpool (4 runs x 2 local-d) + bias + writeout: 4 dpl x 96 c ----
        if (tid < 384) {
            int dpl = tid & 3;
            int cc  = tid >> 2;
            float m = -CUDART_INF_F;
#pragma unroll
            for (int r = 0; r < 4; ++r)
#pragma unroll
                for (int dd = 0; dd < 2; ++dd)
                    m = fmaxf(m, Ys[(r * 8 + 2 * dpl + dd) * 100 + cc]);
            m += bsm[cc];
            int row = ((b * 16 + hp) * 16 + wp) * 16 + dq * 4 + dpl;
            if (cc < 16) {
                __nv_bfloat16 b0 = __float2bfloat16(m);
                g_Fb0[row * 16 + cc] = b0;
                g_Fb1[row * 16 + cc] = __float2bfloat16(m - __bfloat162float(b0));
            } else if (cc < 32) {
                g_G[row * 16 + (cc - 16)] = m;
            } else {
                g_Ht[b][cc - 32][row & (NPB - 1)] = __uint_as_float(f2tf32(m));
            }
        }
    }
}

// =============================================================================
// Kernel C: flash attention; MMA1 = 3x bf16, MMA2 = tf32 with raw fp32 P
// (HW truncates to tf32; l sums the same raw values so normalization cancels).
// Grid (qb=64, ks=4), 256 threads, occ 2. (R12 version, kept.)
// =============================================================================
__global__ void __launch_bounds__(256, 2) kattn()
{
    extern __shared__ float sm[];
    const uint32_t smb = smem_u32(sm);

    const int tid = threadIdx.x;
    const int w = tid >> 5, lane = tid & 31;
    const int lr = lane >> 2, lc = lane & 3;
    const int wm = w >> 1, wn = w & 1;

    const int qb = blockIdx.x, ks = blockIdx.y;
    const int rows0 = qb * 128 + wm * 32;
    const int b = qb >> 5;
    const int kloc0 = ks * (NPB / KS_C);
    const long kg0 = (long)b * NPB + kloc0;

    float* Pw = sm + SM2_P + wm * (32 * 68);
    const uint32_t PwB = smb + (uint32_t)((SM2_P + wm * 32 * 68) * 4);
    float* s_l0 = sm + SM2_LS;
    float* s_l1 = sm + SM2_LS + 128;

    uint32_t qb0[2][4], qb1[2][4];
#pragma unroll
    for (int ml = 0; ml < 2; ++ml) {
        int r0 = rows0 + ml * 16;
#pragma unroll
        for (int j = 0; j < 4; ++j) {
            int row = r0 + lr + (j & 1) * 8;
            int c0  = 2 * lc + (j >> 1) * 8;
            float2 v = *(const float2*)&g_G[(long)row * 16 + c0];
            __nv_bfloat16 h0 = __float2bfloat16(v.x);
            __nv_bfloat16 h1 = __float2bfloat16(v.y);
            qb0[ml][j] = packbf2(v.x, v.y);
            qb1[ml][j] = packbf2(v.x - __bfloat162float(h0),
                                 v.y - __bfloat162float(h1));
        }
    }

    float o[2][4][4];
#pragma unroll
    for (int ml = 0; ml < 2; ++ml)
#pragma unroll
        for (int t = 0; t < 4; ++t)
#pragma unroll
            for (int i = 0; i < 4; ++i) o[ml][t][i] = 0.f;
    float ls[2][2] = {{0.f, 0.f}, {0.f, 0.f}};

    {
        uint32_t base = smb;
        int key = tid >> 2, sc = tid & 3;
        int spl = sc >> 1, ch = sc & 1;
        const __nv_bfloat16* gF = spl ? g_Fb1 : g_Fb0;
        cp16(base + (uint32_t)(spl * 3072 + key * 48 + ch * 16),
             (const char*)(gF + (kg0 + key) * 16) + ch * 16);
#pragma unroll
        for (int r = 0; r < 4; ++r) {
            int i = r * 256 + tid;
            int c = i >> 4, kc = i & 15;
            cp16(base + (uint32_t)((SM2_VT + c * 68 + kc * 4) * 4),
                 (const char*)&g_Ht[b][c][kloc0 + kc * 4]);
        }
        CP_COMMIT();
    }

    for (int kb = 0; kb < NB; ++kb) {
        __syncthreads();
        if (kb + 1 < NB) {
            const int kl = kloc0 + (kb + 1) * 64;
            const long kg = (long)b * NPB + kl;
            uint32_t base = smb + (uint32_t)(((kb + 1) & 1) * SM2_BUF * 4);
            int key = tid >> 2, sc = tid & 3;
            int spl = sc >> 1, ch = sc & 1;
            const __nv_bfloat16* gF = spl ? g_Fb1 : g_Fb0;
            cp16(base + (uint32_t)(spl * 3072 + key * 48 + ch * 16),
                 (const char*)(gF + (kg + key) * 16) + ch * 16);
#pragma unroll
            for (int r = 0; r < 4; ++r) {
                int i = r * 256 + tid;
                int c = i >> 4, kc = i & 15;
                cp16(base + (uint32_t)((SM2_VT + c * 68 + kc * 4) * 4),
                     (const char*)&g_Ht[b][c][kl + kc * 4]);
            }
            CP_COMMIT();
            CP_WAIT(1);
        } else {
            CP_WAIT(0);
        }
        __syncthreads();

        const uint32_t bufB = smb + (uint32_t)((kb & 1) * SM2_BUF * 4);

        // ---- MMA1 (bf16) + exp + P store ----
#pragma unroll
        for (int p = 0; p < 2; ++p) {
            uint32_t rowk = (uint32_t)(((wn * 4 + 2 * p) * 8 + (lane & 7)
                                        + (lane >> 4) * 8) * 48
                                       + ((lane >> 3) & 1) * 16);
            uint32_t fb0[4], fb1[4];
            ldm_x4(fb0, bufB + rowk);
            ldm_x4(fb1, bufB + 3072u + rowk);
#pragma unroll
            for (int i2 = 0; i2 < 2; ++i2) {
                const int ktg = wn * 4 + 2 * p + i2;
#pragma unroll
                for (int ml = 0; ml < 2; ++ml) {
                    float acc[4] = {0.f, 0.f, 0.f, 0.f};
                    mma_bf16(acc, qb0[ml], fb0 + 2 * i2);
                    mma_bf16(acc, qb0[ml], fb1 + 2 * i2);
                    mma_bf16(acc, qb1[ml], fb0 + 2 * i2);
                    float p0 = __expf(acc[0]);
                    float p1 = __expf(acc[1]);
                    float p2 = __expf(acc[2]);
                    float p3 = __expf(acc[3]);
                    ls[ml][0] += p0 + p1;
                    ls[ml][1] += p2 + p3;
                    *(float2*)&Pw[(ml * 16 + lr) * 68 + ktg * 8 + 2 * lc] =
                        make_float2(p0, p1);
                    *(float2*)&Pw[(ml * 16 + lr + 8) * 68 + ktg * 8 + 2 * lc] =
                        make_float2(p2, p3);
                }
            }
        }

        asm volatile("bar.sync %0, 64;" :: "r"(1 + wm) : "memory");

        // ---- MMA2 (tf32): O += P.V ----
#pragma unroll
        for (int kk = 0; kk < 8; ++kk) {
            uint32_t pa[2][4];
#pragma unroll
            for (int ml = 0; ml < 2; ++ml) {
                uint32_t addr = PwB + (uint32_t)(((ml * 16 + (lane & 7) + ((lane >> 3) & 1) * 8) * 68
                                 + kk * 8 + (lane >> 4) * 4) * 4);
                ldm_x4(pa[ml], addr);
            }
#pragma unroll
            for (int ctp = 0; ctp < 2; ++ctp) {
                uint32_t vb[4];
                uint32_t addr = bufB + (uint32_t)((SM2_VT
                                 + ((wn * 4 + ctp * 2) * 8 + (lane >> 4) * 8 + (lane & 7)) * 68
                                 + kk * 8 + ((lane >> 3) & 1) * 4) * 4);
                ldm_x4(vb, addr);
#pragma unroll
                for (int ml = 0; ml < 2; ++ml) {
                    mma_tf32(o[ml][ctp * 2 + 0], pa[ml], vb);
                    mma_tf32(o[ml][ctp * 2 + 1], pa[ml], vb + 2);
                }
            }
        }
    }

    // ---- epilogue ----
#pragma unroll
    for (int ml = 0; ml < 2; ++ml)
#pragma unroll
        for (int hh = 0; hh < 2; ++hh) {
            float v = ls[ml][hh];
            v += __shfl_xor_sync(0xffffffffu, v, 1);
            v += __shfl_xor_sync(0xffffffffu, v, 2);
            ls[ml][hh] = v;
        }
    if (lc == 0) {
        float* dst = wn ? s_l1 : s_l0;
#pragma unroll
        for (int ml = 0; ml < 2; ++ml) {
            dst[wm * 32 + ml * 16 + lr]     = ls[ml][0];
            dst[wm * 32 + ml * 16 + lr + 8] = ls[ml][1];
        }
    }
    __syncthreads();
    if (tid < 128)
        g_Ls[ks * NROW + qb * 128 + tid] = s_l0[tid] + s_l1[tid];

#pragma unroll
    for (int ml = 0; ml < 2; ++ml)
#pragma unroll
        for (int ct = 0; ct < 4; ++ct) {
            int r0 = rows0 + ml * 16;
            int c0 = wn * 32 + ct * 8 + 2 * lc;
            *(float2*)&g_O[ks][(long)(r0 + lr) * 64 + c0] =
                make_float2(o[ml][ct][0], o[ml][ct][1]);
            *(float2*)&g_O[ks][(long)(r0 + lr + 8) * 64 + c0] =
                make_float2(o[ml][ct][2], o[ml][ct][3]);
        }
}

// =============================================================================
// Kernel E (fused): merge key-splits, U = o @ Wv + bv at pooled res, then
// out = gamma * upsample(U) + x written directly.
// =============================================================================
__global__ void __launch_bounds__(128) kout(const float* __restrict__ Wv,
                                           const float* __restrict__ bv,
                                           const float* __restrict__ x,
                                           const float* __restrict__ gamma,
                                           float* __restrict__ out)
{
    __shared__ float os[16 * 64];
    __shared__ float linv[16];
    const int row0 = blockIdx.x * 16;
    const int tid = threadIdx.x;

    if (tid < 16) {
        int r = row0 + tid;
        float l = 0.f;
#pragma unroll
        for (int s = 0; s < KS_C; ++s) l += g_Ls[s * NROW + r];
        linv[tid] = 1.f / l;
    }
    __syncthreads();

    for (int i = tid; i < 1024; i += 128) {
        int rlc = i >> 6;
        float ssum = 0.f;
#pragma unroll
        for (int s = 0; s < KS_C; ++s) ssum += g_O[s][(long)row0 * 64 + i];
        os[i] = ssum * linv[rlc];
    }
    __syncthreads();

    float acc[16];
    const float bb = bv[tid];
#pragma unroll
    for (int n = 0; n < 16; ++n) acc[n] = bb;

    for (int k = 0; k < 64; ++k) {
        float wv = Wv[k * 128 + tid];
#pragma unroll
        for (int n = 0; n < 16; ++n) acc[n] += os[n * 64 + k] * wv;
    }

    const float g = __ldg(gamma);
#pragma unroll
    for (int n = 0; n < 16; ++n) {
        int row = row0 + n;
        int b = row >> 12, hp = (row >> 8) & 15, wp = (row >> 4) & 15, dp = row & 15;
        float u = g * acc[n];
#pragma unroll
        for (int v = 0; v < 8; ++v) {
            int hh = v >> 2, ww = (v >> 1) & 1, dd = v & 1;
            long gi = ((((long)b * 32 + 2 * hp + hh) * 32 + 2 * wp + ww) * 32
                       + 2 * dp + dd) * 128 + tid;
            out[gi] = u + x[gi];
        }
    }
}

// =============================================================================
extern "C" void kernel_launch(void* const* d_in, const int* in_sizes, int n_in,
                              void* d_out, int out_size)
{
    const float* x     = (const float*)d_in[0];
    const float* Wf    = (const float*)d_in[1];
    const float* bf    = (const float*)d_in[2];
    const float* Wg    = (const float*)d_in[3];
    const float* bg    = (const float*)d_in[4];
    const float* Wh    = (const float*)d_in[5];
    const float* bh    = (const float*)d_in[6];
    const float* Wv    = (const float*)d_in[7];
    const float* bv    = (const float*)d_in[8];
    const float* gamma = (const float*)d_in[9];
    float* out = (float*)d_out;

    (void)in_sizes; (void)n_in; (void)out_size;

    cudaFuncSetAttribute(kconvpool, cudaFuncAttributeMaxDynamicSharedMemorySize, P3_TOTAL * 4);
    cudaFuncSetAttribute(kattn,     cudaFuncAttributeMaxDynamicSharedMemorySize, SM2_TOTAL * 4);

    kconvpool<<<CGRID, 384, P3_TOTAL * 4>>>(x, Wf, bf, Wg, bg, Wh, bh);
    kattn<<<dim3(64, KS_C), 256, SM2_TOTAL * 4>>>();
    kout<<<512, 128>>>(Wv, bv, x, gamma, out);
}

// round 14
// speedup vs baseline: 1.0384x; 1.0202x over previous
#include <cuda_runtime.h>
#include <cuda_bf16.h>
#include <math_constants.h>
#include <cstdint>

// Problem constants
#define NROW 8192          // B * N  (N = 16^3 pooled voxels per batch)
#define NPB  4096          // rows per batch
#define KS_C 4             // key splits for attention kernel
#define NB   (NPB / (KS_C * 64))   // 16 key-blocks per split
#define NTILE 2048         // conv tiles (16 wp x 16 hp x 2 b x 4 dq)
#define CGRID 296          // persistent conv grid (2 CTAs/SM x 148)
#define LOG2E 1.4426950408889634f

// kattn smem (floats): double buffer of {Fb0[64][12], Fb1[64][12], Vt[64][68]}
#define SM2_FB0  0
#define SM2_FB1  768
#define SM2_VT   1536
#define SM2_BUF  5888
#define SM2_P    (2 * SM2_BUF)          // 11776
#define SM2_LS   (SM2_P + 4 * 32 * 68)  // 20480
#define SM2_TOTAL (SM2_LS + 256)        // 20736 floats = 82944 B

// persistent conv smem layout (floats) — R11 structure
#define P3_WHI 0                        // 96*132 = 12672
#define P3_WLO 12672                    // 32*132 = 4224
#define P3_X   16896                    // 2 x 32*132 = 8448
#define P3_Y   25344                    // 32*100 = 3200
#define P3_B   28544                    // 128
#define P3_TOTAL 28672                  // floats = 114688 B

// ---- mma.sync (sm_80+; works at base sm_100 target) ----
__device__ __forceinline__ void mma_tf32(float* c, const uint32_t* a, const uint32_t* b) {
    asm volatile("mma.sync.aligned.m16n8k8.row.col.f32.tf32.tf32.f32 "
        "{%0,%1,%2,%3}, {%4,%5,%6,%7}, {%8,%9}, {%0,%1,%2,%3};"
        : "+f"(c[0]), "+f"(c[1]), "+f"(c[2]), "+f"(c[3])
        : "r"(a[0]), "r"(a[1]), "r"(a[2]), "r"(a[3]), "r"(b[0]), "r"(b[1]));
}
__device__ __forceinline__ void mma_bf16(float* c, const uint32_t* a, const uint32_t* b) {
    asm volatile("mma.sync.aligned.m16n8k16.row.col.f32.bf16.bf16.f32 "
        "{%0,%1,%2,%3}, {%4,%5,%6,%7}, {%8,%9}, {%0,%1,%2,%3};"
        : "+f"(c[0]), "+f"(c[1]), "+f"(c[2]), "+f"(c[3])
        : "r"(a[0]), "r"(a[1]), "r"(a[2]), "r"(a[3]), "r"(b[0]), "r"(b[1]));
}
__device__ __forceinline__ uint32_t f2tf32(float v) {
    uint32_t r; asm("cvt.rna.tf32.f32 %0, %1;" : "=r"(r) : "f"(v)); return r;
}
__device__ __forceinline__ uint32_t packbf2(float lo, float hi) {
    __nv_bfloat162 t = __floats2bfloat162_rn(lo, hi);
    return *(uint32_t*)&t;
}
__device__ __forceinline__ void ldm_x4(uint32_t* r, uint32_t addr) {
    asm volatile("ldmatrix.sync.aligned.m8n8.x4.shared.b16 {%0,%1,%2,%3}, [%4];"
        : "=r"(r[0]), "=r"(r[1]), "=r"(r[2]), "=r"(r[3]) : "r"(addr));
}
__device__ __forceinline__ void ldm_x2(uint32_t* r, uint32_t addr) {
    asm volatile("ldmatrix.sync.aligned.m8n8.x2.shared.b16 {%0,%1}, [%2];"
        : "=r"(r[0]), "=r"(r[1]) : "r"(addr));
}

__device__ __forceinline__ void cp16(uint32_t dst, const void* src) {
    asm volatile("cp.async.cg.shared.global [%0], [%1], 16;" :: "r"(dst), "l"(src));
}
#define CP_COMMIT() asm volatile("cp.async.commit_group;" ::: "memory")
#define CP_WAIT(n)  asm volatile("cp.async.wait_group %0;" :: "n"(n) : "memory")

__device__ __forceinline__ uint32_t smem_u32(const void* p) {
    uint32_t a;
    asm("{ .reg .u64 t; cvta.to.shared.u64 t, %1; cvt.u32.u64 %0, t; }" : "=r"(a) : "l"(p));
    return a;
}

// ---------------- scratch (static device memory; no allocations) -------------
__device__ __nv_bfloat16 g_Fb0[NROW * 16];   // keys, bf16 primary
__device__ __nv_bfloat16 g_Fb1[NROW * 16];   // keys, bf16 residual
__device__ float g_G[NROW * 16];             // queries (full fp32)
__device__ float g_Ht[2][64][NPB];           // values TRANSPOSED, tf32-rounded
__device__ float g_O[KS_C][NROW * 64];       // partial (unnormalized) attn outputs
__device__ float g_Ls[KS_C * NROW];          // per-split row exp-sum

// =============================================================================
// Kernel A: PERSISTENT tensor-core conv (96 out ch) + 2x2x2 maxpool.
// R11-exact: 256 threads (8 warps, 2m x 4n), cp.async double-buffered X,
// in-loop tf32 hi/lo split, ldmatrix fragment loads, W staged once.
// =============================================================================
__device__ __forceinline__ void stage_x_tile(const float* __restrict__ x,
                                             uint32_t xsb, int buf, int tile, int tid)
{
    const int wp = tile & 15, hp = (tile >> 4) & 15;
    const int q = tile >> 8, b = q >> 2, dq = q & 3;
#pragma unroll
    for (int k = 0; k < 4; ++k) {
        int ci = k * 256 + tid;          // 0..1023 16B chunks
        int run = ci >> 8;               // hh*2+ww
        int d   = (ci >> 5) & 7;
        int c16 = ci & 31;
        int hh = run >> 1, ww = run & 1;
        long gl = ((((long)b * 32 + 2 * hp + hh) * 32 + 2 * wp + ww) * 32
                   + dq * 8 + d) * 128 + c16 * 4;
        cp16(xsb + (uint32_t)((buf * 4224 + (run * 8 + d) * 132 + c16 * 4) * 4),
             (const char*)(x + gl));
    }
}

__global__ void __launch_bounds__(256, 2) kconvpool(
    const float* __restrict__ x,
    const float* __restrict__ Wf, const float* __restrict__ bf,
    const float* __restrict__ Wg, const float* __restrict__ bg,
    const float* __restrict__ Wh, const float* __restrict__ bh)
{
    extern __shared__ float sm[];
    float* Whi = sm + P3_WHI;     // [96][132]
    float* Wlo = sm + P3_WLO;     // [32][132]
    float* Xb  = sm + P3_X;       // [2][32][132]
    float* Ys  = sm + P3_Y;       // [32][100]
    float* bsm = sm + P3_B;       // [96]
    const uint32_t xsb  = smem_u32(Xb);
    const uint32_t whib = smem_u32(Whi);
    const uint32_t wlob = smem_u32(Wlo);

    const int tid = threadIdx.x;
    const int w = tid >> 5, lane = tid & 31;
    const int lr = lane >> 2, lc = lane & 3;
    const int wm = w >> 2, wn = w & 3;
    const int m0 = wm * 16;

    // prefetch first tile while staging W
    stage_x_tile(x, xsb, 0, blockIdx.x, tid);
    CP_COMMIT();

    for (int i = tid; i < 96 * 128; i += 256) {
        int c = i >> 7, k = i & 127;
        float v;
        if (c < 16)      v = Wf[k * 16 + c];
        else if (c < 32) v = Wg[k * 16 + (c - 16)];
        else             v = Wh[k * 64 + (c - 32)];
        float hi = __int_as_float(__float_as_int(v) & 0xffffe000u);
        Whi[c * 132 + k] = hi;
        if (c < 32) Wlo[c * 132 + k] = __uint_as_float(f2tf32(v - hi));
    }
    if (tid < 96)
        bsm[tid] = (tid < 16) ? bf[tid] : (tid < 32 ? bg[tid - 16] : bh[tid - 32]);

    int jbuf = 0;
    for (int tile = blockIdx.x; tile < NTILE; tile += CGRID, jbuf ^= 1) {
        const int nxt = tile + CGRID;
        if (nxt < NTILE) {
            stage_x_tile(x, xsb, jbuf ^ 1, nxt, tid);
            CP_COMMIT();
            CP_WAIT(1);
        } else {
            CP_WAIT(0);
        }
        __syncthreads();   // X(tile) ready; prior epilogue's Y reads done

        const int wp = tile & 15, hp = (tile >> 4) & 15;
        const int q = tile >> 8, b = q >> 2, dq = q & 3;
        const uint32_t xcb = xsb + (uint32_t)(jbuf * 4224 * 4);

        float acc[3][4];
#pragma unroll
        for (int t = 0; t < 3; ++t)
#pragma unroll
            for (int i = 0; i < 4; ++i) acc[t][i] = 0.f;

#pragma unroll
        for (int k0 = 0; k0 < 128; k0 += 8) {
            uint32_t xa[4];
            ldm_x4(xa, xcb + (uint32_t)(((m0 + (lane & 15)) * 132
                                         + k0 + (lane >> 4) * 4) * 4));
            uint32_t ah[4], al[4];
#pragma unroll
            for (int j = 0; j < 4; ++j) {
                float v = __uint_as_float(xa[j]);
                float h = __int_as_float(__float_as_int(v) & 0xffffe000u);
                ah[j] = __float_as_uint(h);
                al[j] = f2tf32(v - h);
            }
#pragma unroll
            for (int tt = 0; tt < 3; ++tt) {
                const int t = wn + tt * 4;
                uint32_t bh2[2];
                ldm_x2(bh2, whib + (uint32_t)(((t * 8 + (lane & 7)) * 132
                                               + k0 + ((lane >> 3) & 1) * 4) * 4));
                mma_tf32(acc[tt], ah, bh2);
                if (tt == 0) {            // t = wn < 4 -> f,g tile (3xtf32)
                    uint32_t bl2[2];
                    ldm_x2(bl2, wlob + (uint32_t)(((t * 8 + (lane & 7)) * 132
                                                   + k0 + ((lane >> 3) & 1) * 4) * 4));
                    mma_tf32(acc[tt], al, bh2);
                    mma_tf32(acc[tt], ah, bl2);
                }
            }
        }

        // ---- C-frags -> Y [voxel][c] (stride 100) ----
#pragma unroll
        for (int tt = 0; tt < 3; ++tt) {
            const int t = wn + tt * 4;
            *(float2*)&Ys[(m0 + lr) * 100 + t * 8 + 2 * lc] =
                make_float2(acc[tt][0], acc[tt][1]);
            *(float2*)&Ys[(m0 + lr + 8) * 100 + t * 8 + 2 * lc] =
                make_float2(acc[tt][2], acc[tt][3]);
        }
        __syncthreads();

        // ---- maxpool + bias + writeout: 4 dpl x 96 c ----
        for (int i = tid; i < 384; i += 256) {
            int dpl = i & 3;
            int cc  = i >> 2;
            float m = -CUDART_INF_F;
#pragma unroll
            for (int r = 0; r < 4; ++r)
#pragma unroll
                for (int dd = 0; dd < 2; ++dd)
                    m = fmaxf(m, Ys[(r * 8 + 2 * dpl + dd) * 100 + cc]);
            m += bsm[cc];
            int row = ((b * 16 + hp) * 16 + wp) * 16 + dq * 4 + dpl;
            if (cc < 16) {
                __nv_bfloat16 b0 = __float2bfloat16(m);
                g_Fb0[row * 16 + cc] = b0;
                g_Fb1[row * 16 + cc] = __float2bfloat16(m - __bfloat162float(b0));
            } else if (cc < 32) {
                g_G[row * 16 + (cc - 16)] = m;
            } else {
                g_Ht[b][cc - 32][row & (NPB - 1)] = __uint_as_float(f2tf32(m));
            }
        }
    }
}

// =============================================================================
// Kernel C: flash attention; MMA1 = 3x bf16 with Q pre-scaled by log2(e) so
// exp(s) == exp2(s') with a single MUFU.EX2 (no FMUL); MMA2 = tf32 with
// rn-rounded P (f2tf32) — l sums the same rounded values so normalization
// is exact. Grid (qb=64, ks=4), 256 threads, occ 2.
// =============================================================================
__global__ void __launch_bounds__(256, 2) kattn()
{
    extern __shared__ float sm[];
    const uint32_t smb = smem_u32(sm);

    const int tid = threadIdx.x;
    const int w = tid >> 5, lane = tid & 31;
    const int lr = lane >> 2, lc = lane & 3;
    const int wm = w >> 1, wn = w & 1;

    const int qb = blockIdx.x, ks = blockIdx.y;
    const int rows0 = qb * 128 + wm * 32;
    const int b = qb >> 5;
    const int kloc0 = ks * (NPB / KS_C);
    const long kg0 = (long)b * NPB + kloc0;

    float* Pw = sm + SM2_P + wm * (32 * 68);
    const uint32_t PwB = smb + (uint32_t)((SM2_P + wm * 32 * 68) * 4);
    float* s_l0 = sm + SM2_LS;
    float* s_l1 = sm + SM2_LS + 128;

    // ---- Q bf16 A-fragments, pre-scaled by log2(e), value+residual ----
    uint32_t qb0[2][4], qb1[2][4];
#pragma unroll
    for (int ml = 0; ml < 2; ++ml) {
        int r0 = rows0 + ml * 16;
#pragma unroll
        for (int j = 0; j < 4; ++j) {
            int row = r0 + lr + (j & 1) * 8;
            int c0  = 2 * lc + (j >> 1) * 8;
            float2 v = *(const float2*)&g_G[(long)row * 16 + c0];
            v.x *= LOG2E; v.y *= LOG2E;
            __nv_bfloat16 h0 = __float2bfloat16(v.x);
            __nv_bfloat16 h1 = __float2bfloat16(v.y);
            qb0[ml][j] = packbf2(v.x, v.y);
            qb1[ml][j] = packbf2(v.x - __bfloat162float(h0),
                                 v.y - __bfloat162float(h1));
        }
    }

    float o[2][4][4];
#pragma unroll
    for (int ml = 0; ml < 2; ++ml)
#pragma unroll
        for (int t = 0; t < 4; ++t)
#pragma unroll
            for (int i = 0; i < 4; ++i) o[ml][t][i] = 0.f;
    float ls[2][2] = {{0.f, 0.f}, {0.f, 0.f}};

    {
        uint32_t base = smb;
        int key = tid >> 2, sc = tid & 3;
        int spl = sc >> 1, ch = sc & 1;
        const __nv_bfloat16* gF = spl ? g_Fb1 : g_Fb0;
        cp16(base + (uint32_t)(spl * 3072 + key * 48 + ch * 16),
             (const char*)(gF + (kg0 + key) * 16) + ch * 16);
#pragma unroll
        for (int r = 0; r < 4; ++r) {
            int i = r * 256 + tid;
            int c = i >> 4, kc = i & 15;
            cp16(base + (uint32_t)((SM2_VT + c * 68 + kc * 4) * 4),
                 (const char*)&g_Ht[b][c][kloc0 + kc * 4]);
        }
        CP_COMMIT();
    }

    for (int kb = 0; kb < NB; ++kb) {
        __syncthreads();
        if (kb + 1 < NB) {
            const int kl = kloc0 + (kb + 1) * 64;
            const long kg = (long)b * NPB + kl;
            uint32_t base = smb + (uint32_t)(((kb + 1) & 1) * SM2_BUF * 4);
            int key = tid >> 2, sc = tid & 3;
            int spl = sc >> 1, ch = sc & 1;
            const __nv_bfloat16* gF = spl ? g_Fb1 : g_Fb0;
            cp16(base + (uint32_t)(spl * 3072 + key * 48 + ch * 16),
                 (const char*)(gF + (kg + key) * 16) + ch * 16);
#pragma unroll
            for (int r = 0; r < 4; ++r) {
                int i = r * 256 + tid;
                int c = i >> 4, kc = i & 15;
                cp16(base + (uint32_t)((SM2_VT + c * 68 + kc * 4) * 4),
                     (const char*)&g_Ht[b][c][kl + kc * 4]);
            }
            CP_COMMIT();
            CP_WAIT(1);
        } else {
            CP_WAIT(0);
        }
        __syncthreads();

        const uint32_t bufB = smb + (uint32_t)((kb & 1) * SM2_BUF * 4);

        // ---- MMA1 (bf16) + exp2 + P store ----
#pragma unroll
        for (int p = 0; p < 2; ++p) {
            uint32_t rowk = (uint32_t)(((wn * 4 + 2 * p) * 8 + (lane & 7)
                                        + (lane >> 4) * 8) * 48
                                       + ((lane >> 3) & 1) * 16);
            uint32_t fb0[4], fb1[4];
            ldm_x4(fb0, bufB + rowk);
            ldm_x4(fb1, bufB + 3072u + rowk);
#pragma unroll
            for (int i2 = 0; i2 < 2; ++i2) {
                const int ktg = wn * 4 + 2 * p + i2;
#pragma unroll
                for (int ml = 0; ml < 2; ++ml) {
                    float acc[4] = {0.f, 0.f, 0.f, 0.f};
                    mma_bf16(acc, qb0[ml], fb0 + 2 * i2);
                    mma_bf16(acc, qb0[ml], fb1 + 2 * i2);
                    mma_bf16(acc, qb1[ml], fb0 + 2 * i2);
                    uint32_t p0 = f2tf32(exp2f(acc[0]));
                    uint32_t p1 = f2tf32(exp2f(acc[1]));
                    uint32_t p2 = f2tf32(exp2f(acc[2]));
                    uint32_t p3 = f2tf32(exp2f(acc[3]));
                    ls[ml][0] += __uint_as_float(p0) + __uint_as_float(p1);
                    ls[ml][1] += __uint_as_float(p2) + __uint_as_float(p3);
                    *(float2*)&Pw[(ml * 16 + lr) * 68 + ktg * 8 + 2 * lc] =
                        make_float2(__uint_as_float(p0), __uint_as_float(p1));
                    *(float2*)&Pw[(ml * 16 + lr + 8) * 68 + ktg * 8 + 2 * lc] =
                        make_float2(__uint_as_float(p2), __uint_as_float(p3));
                }
            }
        }

        asm volatile("bar.sync %0, 64;" :: "r"(1 + wm) : "memory");

        // ---- MMA2 (tf32): O += P.V ----
#pragma unroll
        for (int kk = 0; kk < 8; ++kk) {
            uint32_t pa[2][4];
#pragma unroll
            for (int ml = 0; ml < 2; ++ml) {
                uint32_t addr = PwB + (uint32_t)(((ml * 16 + (lane & 7) + ((lane >> 3) & 1) * 8) * 68
                                 + kk * 8 + (lane >> 4) * 4) * 4);
                ldm_x4(pa[ml], addr);
            }
#pragma unroll
            for (int ctp = 0; ctp < 2; ++ctp) {
                uint32_t vb[4];
                uint32_t addr = bufB + (uint32_t)((SM2_VT
                                 + ((wn * 4 + ctp * 2) * 8 + (lane >> 4) * 8 + (lane & 7)) * 68
                                 + kk * 8 + ((lane >> 3) & 1) * 4) * 4);
                ldm_x4(vb, addr);
#pragma unroll
                for (int ml = 0; ml < 2; ++ml) {
                    mma_tf32(o[ml][ctp * 2 + 0], pa[ml], vb);
                    mma_tf32(o[ml][ctp * 2 + 1], pa[ml], vb + 2);
                }
            }
        }
    }

    // ---- epilogue ----
#pragma unroll
    for (int ml = 0; ml < 2; ++ml)
#pragma unroll
        for (int hh = 0; hh < 2; ++hh) {
            float v = ls[ml][hh];
            v += __shfl_xor_sync(0xffffffffu, v, 1);
            v += __shfl_xor_sync(0xffffffffu, v, 2);
            ls[ml][hh] = v;
        }
    if (lc == 0) {
        float* dst = wn ? s_l1 : s_l0;
#pragma unroll
        for (int ml = 0; ml < 2; ++ml) {
            dst[wm * 32 + ml * 16 + lr]     = ls[ml][0];
            dst[wm * 32 + ml * 16 + lr + 8] = ls[ml][1];
        }
    }
    __syncthreads();
    if (tid < 128)
        g_Ls[ks * NROW + qb * 128 + tid] = s_l0[tid] + s_l1[tid];

#pragma unroll
    for (int ml = 0; ml < 2; ++ml)
#pragma unroll
        for (int ct = 0; ct < 4; ++ct) {
            int r0 = rows0 + ml * 16;
            int c0 = wn * 32 + ct * 8 + 2 * lc;
            *(float2*)&g_O[ks][(long)(r0 + lr) * 64 + c0] =
                make_float2(o[ml][ct][0], o[ml][ct][1]);
            *(float2*)&g_O[ks][(long)(r0 + lr + 8) * 64 + c0] =
                make_float2(o[ml][ct][2], o[ml][ct][3]);
        }
}

// =============================================================================
// Kernel E (fused): merge key-splits, U = o @ Wv + bv at pooled res, then
// out = gamma * upsample(U) + x written directly.
// =============================================================================
__global__ void __launch_bounds__(128) kout(const float* __restrict__ Wv,
                                           const float* __restrict__ bv,
                                           const float* __restrict__ x,
                                           const float* __restrict__ gamma,
                                           float* __restrict__ out)
{
    __shared__ float os[16 * 64];
    __shared__ float linv[16];
    const int row0 = blockIdx.x * 16;
    const int tid = threadIdx.x;

    if (tid < 16) {
        int r = row0 + tid;
        float l = 0.f;
#pragma unroll
        for (int s = 0; s < KS_C; ++s) l += g_Ls[s * NROW + r];
        linv[tid] = 1.f / l;
    }
    __syncthreads();

    for (int i = tid; i < 1024; i += 128) {
        int rlc = i >> 6;
        float ssum = 0.f;
#pragma unroll
        for (int s = 0; s < KS_C; ++s) ssum += g_O[s][(long)row0 * 64 + i];
        os[i] = ssum * linv[rlc];
    }
    __syncthreads();

    float acc[16];
    const float bb = bv[tid];
#pragma unroll
    for (int n = 0; n < 16; ++n) acc[n] = bb;

    for (int k = 0; k < 64; ++k) {
        float wv = Wv[k * 128 + tid];
#pragma unroll
        for (int n = 0; n < 16; ++n) acc[n] += os[n * 64 + k] * wv;
    }

    const float g = __ldg(gamma);
#pragma unroll
    for (int n = 0; n < 16; ++n) {
        int row = row0 + n;
        int b = row >> 12, hp = (row >> 8) & 15, wp = (row >> 4) & 15, dp = row & 15;
        float u = g * acc[n];
#pragma unroll
        for (int v = 0; v < 8; ++v) {
            int hh = v >> 2, ww = (v >> 1) & 1, dd = v & 1;
            long gi = ((((long)b * 32 + 2 * hp + hh) * 32 + 2 * wp + ww) * 32
                       + 2 * dp + dd) * 128 + tid;
            out[gi] = u + x[gi];
        }
    }
}

// =============================================================================
extern "C" void kernel_launch(void* const* d_in, const int* in_sizes, int n_in,
                              void* d_out, int out_size)
{
    const float* x     = (const float*)d_in[0];
    const float* Wf    = (const float*)d_in[1];
    const float* bf    = (const float*)d_in[2];
    const float* Wg    = (const float*)d_in[3];
    const float* bg    = (const float*)d_in[4];
    const float* Wh    = (const float*)d_in[5];
    const float* bh    = (const float*)d_in[6];
    const float* Wv    = (const float*)d_in[7];
    const float* bv    = (const float*)d_in[8];
    const float* gamma = (const float*)d_in[9];
    float* out = (float*)d_out;

    (void)in_sizes; (void)n_in; (void)out_size;

    cudaFuncSetAttribute(kconvpool, cudaFuncAttributeMaxDynamicSharedMemorySize, P3_TOTAL * 4);
    cudaFuncSetAttribute(kattn,     cudaFuncAttributeMaxDynamicSharedMemorySize, SM2_TOTAL * 4);

    kconvpool<<<CGRID, 256, P3_TOTAL * 4>>>(x, Wf, bf, Wg, bg, Wh, bh);
    kattn<<<dim3(64, KS_C), 256, SM2_TOTAL * 4>>>();
    kout<<<512, 128>>>(Wv, bv, x, gamma, out);
}